// round 11
// baseline (speedup 1.0000x reference)
#include <cuda_runtime.h>
#include <cuda_fp16.h>
#include <cstdint>

// NearestNeighborGraph: 16 samples x 2048 points x 64 dims, K=16.
// Output (float32): [knn_dist | dst | src], each 16*2048*16.
//
// fp16 2-term-split mma.sync Gram tiles; cp.async double-buffered B tiles
// (prefetch tile t+1 during tile t); single SMEM distance half-buffer;
// min8-grouped top-16 sorted-insert scan. 2 CTAs/SM.

#define NS     16
#define NP     2048
#define DIMS   64
#define KNN    16
#define TM     128
#define TN     128
#define NTILES (NP / TN)
#define OUTBLK (NS * NP * KNN)

#define PITCHB 144           // smem row pitch bytes (9x16B, ldmatrix conflict-free)
#define PITCHQ 9             // uint4 per row
#define TILEQ  (TM * PITCHQ) // 1152 uint4 = 18432 B per term plane
#define DPITCH 68            // dist half-tile row pitch in floats (64+4)

// SMEM layout (bytes)
#define SM_B0  0                    // hi at +0, lo at +18432
#define SM_B1  36864
#define SM_LO  18432                // lo-plane offset within a B buffer
#define SM_D   73728                // 128*68*4 = 34816
#define SM_CN0 108544
#define SM_CN1 109056
#define SM_TOT 109568

__device__ uint4 g_h16[NS * NP * PITCHQ];  // fp16 hi plane, 144B pitch
__device__ uint4 g_l16[NS * NP * PITCHQ];  // fp16 lo plane
__device__ float g_x2[NS * NP];            // fp32 norms

// ---------------- helpers ----------------
__device__ __forceinline__ uint32_t smem_u32(const void* p) {
    uint32_t a;
    asm("{ .reg .u64 t; cvta.to.shared.u64 t, %1; cvt.u32.u64 %0, t; }"
        : "=r"(a) : "l"(p));
    return a;
}

__device__ __forceinline__ void ldsm4(uint32_t* r, uint32_t addr) {
    asm volatile("ldmatrix.sync.aligned.m8n8.x4.shared.b16 {%0,%1,%2,%3}, [%4];"
                 : "=r"(r[0]), "=r"(r[1]), "=r"(r[2]), "=r"(r[3]) : "r"(addr));
}

__device__ __forceinline__ void mma16816(float* d, const uint32_t* a,
                                         const uint32_t* b) {
    asm volatile(
        "mma.sync.aligned.m16n8k16.row.col.f32.f16.f16.f32 "
        "{%0,%1,%2,%3}, {%4,%5,%6,%7}, {%8,%9}, {%0,%1,%2,%3};"
        : "+f"(d[0]), "+f"(d[1]), "+f"(d[2]), "+f"(d[3])
        : "r"(a[0]), "r"(a[1]), "r"(a[2]), "r"(a[3]), "r"(b[0]), "r"(b[1]));
}

__device__ __forceinline__ void cp16(uint32_t saddr, const void* gaddr) {
    asm volatile("cp.async.cg.shared.global [%0], [%1], 16;"
                 :: "r"(saddr), "l"(gaddr));
}
__device__ __forceinline__ void cp4(uint32_t saddr, const void* gaddr) {
    asm volatile("cp.async.ca.shared.global [%0], [%1], 4;"
                 :: "r"(saddr), "l"(gaddr));
}
#define CP_COMMIT() asm volatile("cp.async.commit_group;" ::: "memory")
#define CP_WAIT0()  asm volatile("cp.async.wait_group 0;" ::: "memory")

__device__ __forceinline__ uint32_t pack_h2(__half lo, __half hi) {
    __half2 h = __halves2half2(lo, hi);
    return *reinterpret_cast<uint32_t*>(&h);
}

// Float sorted insert; strict '<' + increasing per-thread scan order => stable
// ties toward the smaller index (lax.top_k semantics).
#define INSERTF(dval, idx) do {                                                \
    if ((dval) < dk[KNN - 1]) {                                                \
        dk[KNN - 1] = (dval);                                                  \
        ik[KNN - 1] = (idx);                                                   \
        _Pragma("unroll")                                                      \
        for (int _t = KNN - 1; _t > 0; --_t) {                                 \
            if (dk[_t] < dk[_t - 1]) {                                         \
                float _fd = dk[_t]; dk[_t] = dk[_t - 1]; dk[_t - 1] = _fd;     \
                int   _fi = ik[_t]; ik[_t] = ik[_t - 1]; ik[_t - 1] = _fi;     \
            }                                                                  \
        }                                                                      \
    }                                                                          \
} while (0)

// ---------------- prologue: fp16 split planes + norms ----------------
__global__ void __launch_bounds__(256) prep_kernel(const float* __restrict__ h) {
    int r = blockIdx.x * blockDim.x + threadIdx.x;
    if (r >= NS * NP) return;
    const float4* src = reinterpret_cast<const float4*>(h + (size_t)r * DIMS);
    float s = 0.f;
#pragma unroll
    for (int q = 0; q < 8; ++q) {
        float4 x0 = src[2 * q];
        float4 x1 = src[2 * q + 1];
        float f[8] = {x0.x, x0.y, x0.z, x0.w, x1.x, x1.y, x1.z, x1.w};
        uint32_t rh[4], rl[4];
#pragma unroll
        for (int e = 0; e < 4; ++e) {
            float a = f[2 * e], c = f[2 * e + 1];
            __half ah = __float2half_rn(a), ch = __float2half_rn(c);
            float al = a - __half2float(ah);
            float cl = c - __half2float(ch);
            rh[e] = pack_h2(ah, ch);
            rl[e] = pack_h2(__float2half_rn(al), __float2half_rn(cl));
            s += a * a;
            s += c * c;
        }
        g_h16[(size_t)r * PITCHQ + q] = make_uint4(rh[0], rh[1], rh[2], rh[3]);
        g_l16[(size_t)r * PITCHQ + q] = make_uint4(rl[0], rl[1], rl[2], rl[3]);
    }
    g_h16[(size_t)r * PITCHQ + 8] = make_uint4(0, 0, 0, 0);
    g_l16[(size_t)r * PITCHQ + 8] = make_uint4(0, 0, 0, 0);
    g_x2[r] = s;
}

// ---------------- main kernel ----------------
__global__ void __launch_bounds__(256, 2) knn_kernel(float* __restrict__ out,
                                                     int write_edges) {
    extern __shared__ char smem[];
    const uint32_t sb = smem_u32(smem);
    const int tid  = threadIdx.x;
    const int w    = tid >> 5;
    const int lane = tid & 31;
    const int tg   = lane & 3;
    const int g    = lane >> 2;
    const int b    = blockIdx.y;
    const int qbase = blockIdx.x * TM;

    // ---- stage A (query) planes into B1 (regular copy, once) ----
    {
        const uint4* srcH = g_h16 + (size_t)(b * NP + qbase) * PITCHQ;
        const uint4* srcL = g_l16 + (size_t)(b * NP + qbase) * PITCHQ;
        uint4* dA = reinterpret_cast<uint4*>(smem + SM_B1);
        for (int i = tid; i < TILEQ; i += 256) {
            dA[i]                    = srcH[i];
            dA[TILEQ + i]            = srcL[i];
        }
    }
    __syncthreads();

    // ---- cache A fragments (fixed for whole CTA) ----
    uint32_t Ah[4][4], Al[4][4];
    {
        uint32_t a_off = sb + SM_B1 + (uint32_t)(w * 16 + (lane & 15)) * PITCHB +
                         (uint32_t)(lane >> 4) * 16;
#pragma unroll
        for (int k = 0; k < 4; ++k) {
            ldsm4(Ah[k], a_off + k * 32);
            ldsm4(Al[k], a_off + SM_LO + k * 32);
        }
    }
    const int row0 = w * 16 + g;
    const float qn0 = g_x2[b * NP + qbase + row0];
    const float qn1 = g_x2[b * NP + qbase + row0 + 8];

    const int srow = tid >> 1;
    const int shb  = tid & 1;
    float dk[KNN];
    int   ik[KNN];
#pragma unroll
    for (int k = 0; k < KNN; ++k) { dk[k] = 3.4e38f; ik[k] = 0; }

    const uint32_t b_lane_off =
        (uint32_t)(((lane & 7) + ((lane >> 4) << 3)) * PITCHB) +
        ((lane & 8) ? 16u : 0u);
    float* distf = reinterpret_cast<float*>(smem + SM_D);

    // ---- prefetch tile 0 into B0 / CN0 ----
    {
        const uint4* sH = g_h16 + (size_t)(b * NP) * PITCHQ;
        const uint4* sL = g_l16 + (size_t)(b * NP) * PITCHQ;
        for (int i = tid; i < TILEQ; i += 256) {
            cp16(sb + SM_B0 + i * 16,         sH + i);
            cp16(sb + SM_B0 + SM_LO + i * 16, sL + i);
        }
        if (tid < TN) cp4(sb + SM_CN0 + tid * 4, g_x2 + b * NP + tid);
        CP_COMMIT();
        CP_WAIT0();
    }
    __syncthreads();  // frag loads + tile0 copy visible; B1 free

    for (int tt = 0; tt < NTILES; ++tt) {
        const uint32_t curB = sb + ((tt & 1) ? SM_B1 : SM_B0);
        const uint32_t nxtB = sb + ((tt & 1) ? SM_B0 : SM_B1);
        const float* cn = reinterpret_cast<const float*>(
            smem + ((tt & 1) ? SM_CN1 : SM_CN0));

        // ---- prefetch tile tt+1 (overlaps everything below) ----
        if (tt + 1 < NTILES) {
            const uint4* sH = g_h16 + (size_t)(b * NP + (tt + 1) * TN) * PITCHQ;
            const uint4* sL = g_l16 + (size_t)(b * NP + (tt + 1) * TN) * PITCHQ;
            for (int i = tid; i < TILEQ; i += 256) {
                cp16(nxtB + i * 16,         sH + i);
                cp16(nxtB + SM_LO + i * 16, sL + i);
            }
            if (tid < TN)
                cp4(sb + ((tt & 1) ? SM_CN0 : SM_CN1) + tid * 4,
                    g_x2 + b * NP + (tt + 1) * TN + tid);
        }
        CP_COMMIT();

        // ---- computeH0 + fold + store D ----
        {
            float acc[8][4];
#pragma unroll
            for (int nt = 0; nt < 8; ++nt)
#pragma unroll
                for (int e = 0; e < 4; ++e) acc[nt][e] = 0.f;
#pragma unroll
            for (int np = 0; np < 4; ++np) {
#pragma unroll
                for (int k = 0; k < 4; ++k) {
                    uint32_t Bh[4], Bl[4];
                    uint32_t ba = curB + b_lane_off +
                                  (uint32_t)(np * 16 * PITCHB) + (uint32_t)(k * 32);
                    ldsm4(Bh, ba);
                    ldsm4(Bl, ba + SM_LO);
                    mma16816(acc[2 * np],     Ah[k], Bh + 0);
                    mma16816(acc[2 * np],     Ah[k], Bl + 0);
                    mma16816(acc[2 * np],     Al[k], Bh + 0);
                    mma16816(acc[2 * np + 1], Ah[k], Bh + 2);
                    mma16816(acc[2 * np + 1], Ah[k], Bl + 2);
                    mma16816(acc[2 * np + 1], Al[k], Bh + 2);
                }
            }
#pragma unroll
            for (int nt = 0; nt < 8; ++nt) {
                const int c0 = nt * 8 + tg * 2;
                float2 cnp = *reinterpret_cast<const float2*>(cn + c0);
                float2 d0, d1;
                d0.x = fmaf(-2.f, acc[nt][0], qn0 + cnp.x);
                d0.y = fmaf(-2.f, acc[nt][1], qn0 + cnp.y);
                d1.x = fmaf(-2.f, acc[nt][2], qn1 + cnp.x);
                d1.y = fmaf(-2.f, acc[nt][3], qn1 + cnp.y);
                *reinterpret_cast<float2*>(distf + (size_t)row0 * DPITCH + c0) = d0;
                *reinterpret_cast<float2*>(distf + (size_t)(row0 + 8) * DPITCH + c0) = d1;
            }
        }
        __syncthreads();  // D(h0) ready

        // ---- computeH1-MMA (regs only) overlapped with scanH0 ----
        float acc[8][4];
#pragma unroll
        for (int nt = 0; nt < 8; ++nt)
#pragma unroll
            for (int e = 0; e < 4; ++e) acc[nt][e] = 0.f;
#pragma unroll
        for (int np = 0; np < 4; ++np) {
#pragma unroll
            for (int k = 0; k < 4; ++k) {
                uint32_t Bh[4], Bl[4];
                uint32_t ba = curB + b_lane_off +
                              (uint32_t)((64 + np * 16) * PITCHB) + (uint32_t)(k * 32);
                ldsm4(Bh, ba);
                ldsm4(Bl, ba + SM_LO);
                mma16816(acc[2 * np],     Ah[k], Bh + 0);
                mma16816(acc[2 * np],     Ah[k], Bl + 0);
                mma16816(acc[2 * np],     Al[k], Bh + 0);
                mma16816(acc[2 * np + 1], Ah[k], Bh + 2);
                mma16816(acc[2 * np + 1], Ah[k], Bl + 2);
                mma16816(acc[2 * np + 1], Al[k], Bh + 2);
            }
        }
        // scan h0: this thread's 32 cols, min8-grouped
        {
            const float4* drow = reinterpret_cast<const float4*>(
                distf + (size_t)srow * DPITCH + shb * 32);
            const int base = tt * TN + shb * 32;
#pragma unroll 1
            for (int j8 = 0; j8 < 4; ++j8) {
                float4 v0 = drow[2 * j8];
                float4 v1 = drow[2 * j8 + 1];
                float m = fminf(fminf(fminf(v0.x, v0.y), fminf(v0.z, v0.w)),
                                fminf(fminf(v1.x, v1.y), fminf(v1.z, v1.w)));
                if (m < dk[KNN - 1]) {
                    const int idx = base + j8 * 8;
                    INSERTF(v0.x, idx);
                    INSERTF(v0.y, idx + 1);
                    INSERTF(v0.z, idx + 2);
                    INSERTF(v0.w, idx + 3);
                    INSERTF(v1.x, idx + 4);
                    INSERTF(v1.y, idx + 5);
                    INSERTF(v1.z, idx + 6);
                    INSERTF(v1.w, idx + 7);
                }
            }
        }
        __syncthreads();  // scanH0 done -> D reusable

        // ---- foldH1 + store D ----
#pragma unroll
        for (int nt = 0; nt < 8; ++nt) {
            const int c0 = nt * 8 + tg * 2;
            float2 cnp = *reinterpret_cast<const float2*>(cn + 64 + c0);
            float2 d0, d1;
            d0.x = fmaf(-2.f, acc[nt][0], qn0 + cnp.x);
            d0.y = fmaf(-2.f, acc[nt][1], qn0 + cnp.y);
            d1.x = fmaf(-2.f, acc[nt][2], qn1 + cnp.x);
            d1.y = fmaf(-2.f, acc[nt][3], qn1 + cnp.y);
            *reinterpret_cast<float2*>(distf + (size_t)row0 * DPITCH + c0) = d0;
            *reinterpret_cast<float2*>(distf + (size_t)(row0 + 8) * DPITCH + c0) = d1;
        }
        __syncthreads();  // D(h1) ready

        // ---- scan h1 ----
        {
            const float4* drow = reinterpret_cast<const float4*>(
                distf + (size_t)srow * DPITCH + shb * 32);
            const int base = tt * TN + 64 + shb * 32;
#pragma unroll 1
            for (int j8 = 0; j8 < 4; ++j8) {
                float4 v0 = drow[2 * j8];
                float4 v1 = drow[2 * j8 + 1];
                float m = fminf(fminf(fminf(v0.x, v0.y), fminf(v0.z, v0.w)),
                                fminf(fminf(v1.x, v1.y), fminf(v1.z, v1.w)));
                if (m < dk[KNN - 1]) {
                    const int idx = base + j8 * 8;
                    INSERTF(v0.x, idx);
                    INSERTF(v0.y, idx + 1);
                    INSERTF(v0.z, idx + 2);
                    INSERTF(v0.w, idx + 3);
                    INSERTF(v1.x, idx + 4);
                    INSERTF(v1.y, idx + 5);
                    INSERTF(v1.z, idx + 6);
                    INSERTF(v1.w, idx + 7);
                }
            }
        }
        CP_WAIT0();       // tile tt+1 copy landed (own thread's groups)
        __syncthreads();  // all threads waited -> next B visible; D free
    }

    // ---- merge the 2 per-row lists via packed u64 ord-keys ----
    unsigned long long* keys = reinterpret_cast<unsigned long long*>(smem);
#pragma unroll
    for (int k = 0; k < KNN; ++k) {
        uint32_t u = __float_as_uint(dk[k]);
        u ^= (uint32_t)((int)u >> 31) | 0x80000000u;
        keys[((size_t)srow * 2 + shb) * KNN + k] =
            ((unsigned long long)u << 32) | (uint32_t)ik[k];
    }
    __syncthreads();

    if (tid < TM) {
        const int r   = tid;
        const int gqi = b * NP + qbase + r;
        const unsigned long long* L = keys + (size_t)r * 2 * KNN;
        float* od   = out + (size_t)gqi * KNN;
        float* odst = out + OUTBLK + (size_t)gqi * KNN;
        float* osrc = out + 2 * OUTBLK + (size_t)gqi * KNN;
        const float fsrc = (float)gqi;
        int i0 = 0, i1 = 0;
#pragma unroll 1
        for (int k = 0; k < KNN; ++k) {
            unsigned long long h0 = (i0 < KNN) ? L[i0] : ~0ull;
            unsigned long long h1 = (i1 < KNN) ? L[KNN + i1] : ~0ull;
            unsigned long long m;
            if (h0 <= h1) { m = h0; ++i0; } else { m = h1; ++i1; }
            uint32_t o = (uint32_t)(m >> 32);
            uint32_t msk = (o & 0x80000000u) ? 0x80000000u : 0xFFFFFFFFu;
            od[k] = __uint_as_float(o ^ msk);
            if (write_edges) {
                odst[k] = (float)((uint32_t)(m & 0xFFFFFFFFu) + b * NP);
                osrc[k] = fsrc;
            }
        }
    }
}

extern "C" void kernel_launch(void* const* d_in, const int* in_sizes, int n_in,
                              void* d_out, int out_size) {
    const float* h   = (const float*)d_in[0];
    float*       out = (float*)d_out;
    const int write_edges = (out_size >= 3 * OUTBLK) ? 1 : 0;

    cudaFuncSetAttribute(knn_kernel, cudaFuncAttributeMaxDynamicSharedMemorySize,
                         SM_TOT);

    prep_kernel<<<(NS * NP) / 256, 256>>>(h);
    dim3 grid(NP / TM, NS);
    knn_kernel<<<grid, 256, SM_TOT>>>(out, write_edges);
}